// round 3
// baseline (speedup 1.0000x reference)
#include <cuda_runtime.h>
#include <math.h>

#define E   128
#define KC  12
#define BV  4096
#define RD  65536
#define NTILES (RD/128)
#define NSM 152

#define LOG2PI  1.8378770664093453f
#define SQRT2C  1.4142135623730951f
#define SQRTPI  1.7724538509055159f

// ---------------- device globals ----------------
__device__ float g_inv_std[E];
__device__ float g_sum_log_std;
__device__ float g_lsm[KC];
__device__ float g_kA[KC];
__device__ float g_kB[KC];
__device__ float g_kInvS[KC];
__device__ float g_kC[KC];
__device__ float g_kHL[KC];
__device__ float g_kOrthC[KC];
__device__ float g_kI2A[KC];
__device__ float g_P[E*KC];             // Rot^T @ unit_k, [e][k]
__device__ int   g_off[BV+1];
__device__ float g_scratch[(KC+1)*RD];  // [component][read]

// ---------------- K0: constants + prefix scan ----------------
__global__ void k0_consts(const float* __restrict__ stde,
                          const float* __restrict__ mu,
                          const float* __restrict__ sig,
                          const float* __restrict__ lam,
                          const float* __restrict__ asd,
                          const float* __restrict__ w,
                          const int*   __restrict__ counts)
{
    __shared__ float red[4];
    __shared__ int   wsum[16];
    const int t = threadIdx.x;
    const unsigned full = 0xffffffffu;

    float lv = 0.f;
    if (t < E){ float s = stde[t]; g_inv_std[t] = 1.f/s; lv = logf(s); }
    for (int o=16;o>0;o>>=1) lv += __shfl_xor_sync(full, lv, o);
    if (t < E && (t&31)==0) red[t>>5] = lv;

    if (t < KC){
        float m=mu[t], s_=sig[t], l=lam[t], a=asd[t];
        float A = m + l*s_*s_;
        g_kA[t]    = A;
        g_kB[t]    = m + A;
        g_kInvS[t] = 1.f/(SQRT2C*s_);
        g_kC[t]    = logf(0.5f*l);
        g_kHL[t]   = 0.5f*l;
        g_kOrthC[t]= -0.5f*(float)(E-1)*LOG2PI - (float)(E-1)*logf(a);
        g_kI2A[t]  = 1.f/(2.f*a*a);
    }
    if (t==480){
        float mx = -1e30f;
        for (int k=0;k<KC;k++) mx = fmaxf(mx, w[k]);
        float s = 0.f;
        for (int k=0;k<KC;k++) s += expf(w[k]-mx);
        float lse = mx + logf(s);
        for (int k=0;k<KC;k++) g_lsm[k] = w[k] - lse;
    }
    __syncthreads();
    if (t==0) g_sum_log_std = red[0]+red[1]+red[2]+red[3];

    const int base = t*8;
    int c[8]; int s0 = 0;
    #pragma unroll
    for (int i=0;i<8;i++){ c[i] = counts[base+i]; s0 += c[i]; }
    int incl = s0;
    for (int o=1;o<32;o<<=1){
        int v = __shfl_up_sync(full, incl, o);
        if ((t&31) >= o) incl += v;
    }
    if ((t&31)==31) wsum[t>>5] = incl;
    __syncthreads();
    if (t==0){ int run=0; for (int i=0;i<16;i++){ int v=wsum[i]; wsum[i]=run; run+=v; } }
    __syncthreads();
    int run = wsum[t>>5] + incl - s0;
    #pragma unroll
    for (int i=0;i<8;i++){ g_off[base+i] = run; run += c[i]; }
    if (t==511) g_off[BV] = run;
}

// ---------------- K1: P = Rot^T @ unit ----------------
__global__ void k1_proj(const float* __restrict__ rot,
                        const float* __restrict__ dirs)
{
    __shared__ float rcol[E];
    const int e = blockIdx.x, t = threadIdx.x;
    const unsigned full = 0xffffffffu;
    rcol[t] = rot[t*E + e];
    __syncthreads();
    const int w = t>>5, l = t&31;
    #pragma unroll
    for (int kk=0; kk<3; kk++){
        int k = w*3 + kk;
        float ds = 0.f, ns = 0.f;
        #pragma unroll
        for (int j=l; j<E; j+=32){
            float d = dirs[k*E + j];
            ds = fmaf(rcol[j], d, ds);
            ns = fmaf(d, d, ns);
        }
        for (int o=16;o>0;o>>=1){
            ds += __shfl_xor_sync(full, ds, o);
            ns += __shfl_xor_sync(full, ns, o);
        }
        if (l==0) g_P[e*KC + k] = ds * rsqrtf(ns);
    }
}

// ---------------- K2: persistent fused GEMM + per-read log-liks ----------------
#define AS_LD   132
#define SM_B    0
#define SM_A    16896
#define SM_P    33792
#define SM_S2   35328
#define SM_KON  37504
#define SM_T    37588
#define SM_FLOATS 37716
#define SMEM_BYTES (SM_FLOATS*4)

__device__ __forceinline__ unsigned long long dup2(float x){
    unsigned long long r;
    asm("mov.b64 %0, {%1, %1};" : "=l"(r) : "f"(x));
    return r;
}
#define FFMA2(d,a,b) asm("fma.rn.f32x2 %0, %1, %2, %0;" : "+l"(d) : "l"(a), "l"(b))
__device__ __forceinline__ void unpack2(unsigned long long v, float& lo, float& hi){
    asm("mov.b64 {%0, %1}, %2;" : "=f"(lo), "=f"(hi) : "l"(v));
}

__global__ void __launch_bounds__(512,1)
main_kernel(const float* __restrict__ alt,
            const float* __restrict__ trans,
            const float* __restrict__ rot)
{
    extern __shared__ float smem[];
    float* B_s  = smem + SM_B;    // [e][j], ld=132 (Rot^T scaled by 1/sigma_j)
    float* A_s  = smem + SM_A;    // [e][r], ld=132
    float* P_s  = smem + SM_P;    // [e][12]
    float* S2_s = smem + SM_S2;   // [r][17]
    float* KON  = smem + SM_KON;  // 7*12
    float* T_s  = smem + SM_T;    // trans

    const int tid = threadIdx.x;
    const unsigned full = 0xffffffffu;

    // one-time loads
    for (int idx=tid; idx<E*E; idx+=512){
        int j = idx>>7, k = idx&127;
        B_s[k*AS_LD + j] = rot[idx] * g_inv_std[j];
    }
    for (int idx=tid; idx<E*KC; idx+=512) P_s[idx] = g_P[idx];
    if (tid < E) T_s[tid] = trans[tid];
    if (tid < KC){
        KON[tid]    = g_kA[tid];
        KON[12+tid] = g_kB[tid];
        KON[24+tid] = g_kInvS[tid];
        KON[36+tid] = g_kC[tid];
        KON[48+tid] = g_kHL[tid];
        KON[60+tid] = g_kOrthC[tid];
        KON[72+tid] = g_kI2A[tid];
    }
    const float slog = g_sum_log_std;

    const int w = tid>>5, l = tid&31;   // GEMM: warp -> 8-col slab, lane -> 4 rows
    const int r = tid>>2, h = tid&3;    // epilogue: 4 threads per read

    for (int tile = blockIdx.x; tile < NTILES; tile += gridDim.x){
        __syncthreads();   // A_s / S2_s free from previous iteration

        // load translated A tile: A_s[e][rr] = alt[tile*128+rr][e] + trans[e]
        const float* ap = alt + (size_t)tile*128*E;
        #pragma unroll 4
        for (int i=tid; i<E*E; i+=512){
            int rr = i>>7, e = i&127;
            A_s[e*AS_LD + rr] = ap[i] + T_s[e];
        }
        __syncthreads();

        // GEMM: y[rr][j] = sum_e a'[rr][e] * B_s[e][j]
        unsigned long long acc[4][4];
        #pragma unroll
        for (int i=0;i<4;i++)
            #pragma unroll
            for (int j=0;j<4;j++) acc[i][j] = 0ull;

        const float* Ab = A_s + l*4;
        const float* Bb = B_s + w*8;

        #pragma unroll 2
        for (int k=0; k<E; k++){
            float4 a4 = *(const float4*)(Ab + k*AS_LD);          // bank-striped, conflict-free
            ulonglong2 b0 = *(const ulonglong2*)(Bb + k*AS_LD);  // warp-broadcast
            ulonglong2 b1 = *(const ulonglong2*)(Bb + k*AS_LD + 4);
            unsigned long long av[4];
            av[0]=dup2(a4.x); av[1]=dup2(a4.y); av[2]=dup2(a4.z); av[3]=dup2(a4.w);
            unsigned long long bv[4] = {b0.x, b0.y, b1.x, b1.y};
            #pragma unroll
            for (int i=0;i<4;i++){
                #pragma unroll
                for (int j=0;j<4;j++) FFMA2(acc[i][j], av[i], bv[j]);
            }
        }

        // fold s2 partials (y = x/sigma): one float per (row, warp)
        #pragma unroll
        for (int i=0;i<4;i++){
            float s = 0.f;
            #pragma unroll
            for (int j=0;j<4;j++){
                float lo, hi; unpack2(acc[i][j], lo, hi);
                s = fmaf(lo, lo, s);
                s = fmaf(hi, hi, s);
            }
            S2_s[(l*4+i)*17 + w] = s;
        }
        __syncthreads();

        // epilogue: 4 threads per read (same warp), 32 features each
        float nx = 0.f;
        float dot[KC];
        #pragma unroll
        for (int k=0;k<KC;k++) dot[k]=0.f;

        #pragma unroll 4
        for (int cc=0; cc<32; cc++){
            int e = h*32 + cc;
            float a = A_s[e*AS_LD + r];
            nx = fmaf(a, a, nx);
            const float4* pr = (const float4*)(P_s + e*KC);
            float4 p0 = pr[0], p1 = pr[1], p2 = pr[2];
            dot[0]=fmaf(a,p0.x,dot[0]); dot[1]=fmaf(a,p0.y,dot[1]);
            dot[2]=fmaf(a,p0.z,dot[2]); dot[3]=fmaf(a,p0.w,dot[3]);
            dot[4]=fmaf(a,p1.x,dot[4]); dot[5]=fmaf(a,p1.y,dot[5]);
            dot[6]=fmaf(a,p1.z,dot[6]); dot[7]=fmaf(a,p1.w,dot[7]);
            dot[8]=fmaf(a,p2.x,dot[8]); dot[9]=fmaf(a,p2.y,dot[9]);
            dot[10]=fmaf(a,p2.z,dot[10]); dot[11]=fmaf(a,p2.w,dot[11]);
        }
        float s2 = 0.f;
        #pragma unroll
        for (int i=0;i<4;i++) s2 += S2_s[r*17 + h*4 + i];

        // butterfly all-reduce across the 4 threads of this read
        #pragma unroll
        for (int off=1; off<4; off<<=1){
            nx += __shfl_xor_sync(full, nx, off);
            s2 += __shfl_xor_sync(full, s2, off);
            #pragma unroll
            for (int k=0;k<KC;k++) dot[k] += __shfl_xor_sync(full, dot[k], off);
        }

        const int gr = tile*128 + r;
        if (h==0){
            float nonart = -64.f*LOG2PI - slog - 0.5f*s2;
            g_scratch[gr] = nonart;
        }
        // EMG + orth: 3 clusters per thread
        #pragma unroll
        for (int kk=0; kk<3; kk++){
            int k = h*3 + kk;
            float dk    = dot[k];
            float orth2 = nx - dk*dk;
            float oll   = KON[60+k] - orth2*KON[72+k];
            float z     = (KON[k] - dk)*KON[24+k];
            float lec;
            if (z > 5.f){
                float z2=z*z, z4=z2*z2, z6=z4*z2;
                lec = -z2 - logf(z*SQRTPI)
                      + log1pf(-1.f/(2.f*z2) + 3.f/(4.f*z4) - 15.f/(8.f*z6));
            } else {
                lec = logf(erfcf(z));
            }
            float par = KON[36+k] + lec + KON[48+k]*(KON[12+k] - 2.f*dk);
            g_scratch[(size_t)(1+k)*RD + gr] = oll + par;
        }
    }
}

// ---------------- K3: ragged segment sums + logits ----------------
__global__ void reduce_kernel(float* __restrict__ out)
{
    const int b    = blockIdx.x*4 + (threadIdx.x>>5);
    const int lane = threadIdx.x & 31;
    const unsigned full = 0xffffffffu;
    const int lo = g_off[b], hi = g_off[b+1];

    float acc = 0.f;
    if (lane < KC+1){
        const float* p = g_scratch + (size_t)lane*RD;
        float a0=0.f, a1=0.f, a2=0.f, a3=0.f;
        int rr = lo;
        for (; rr+4<=hi; rr+=4){
            a0 += p[rr]; a1 += p[rr+1]; a2 += p[rr+2]; a3 += p[rr+3];
        }
        for (; rr<hi; rr++) a0 += p[rr];
        acc = (a0+a1) + (a2+a3);
        if (lane >= 1) acc += g_lsm[lane-1];
    }
    float nonart = __shfl_sync(full, acc, 0);
    float v = (lane>=1 && lane<KC+1) ? acc : -1e30f;
    float m = v;
    for (int o=16;o>0;o>>=1) m = fmaxf(m, __shfl_xor_sync(full, m, o));
    float e = (lane>=1 && lane<KC+1) ? expf(v-m) : 0.f;
    for (int o=16;o>0;o>>=1) e += __shfl_xor_sync(full, e, o);
    float lse = m + logf(e);
    float logits = lse - nonart;

    if (lane==0)     out[b] = 20.f*tanhf(logits*(1.f/20.f));
    if (lane<KC+1)   out[BV + b*(KC+1) + lane] = acc;
}

// ---------------- launch ----------------
extern "C" void kernel_launch(void* const* d_in, const int* in_sizes, int n_in,
                              void* d_out, int out_size)
{
    const float* alt   = (const float*)d_in[0];
    // d_in[1] = ref_re: unused by the reference output
    const float* trans = (const float*)d_in[2];
    const float* rot   = (const float*)d_in[3];
    const float* stde  = (const float*)d_in[4];
    const float* dirs  = (const float*)d_in[5];
    const float* mu    = (const float*)d_in[6];
    const float* sig   = (const float*)d_in[7];
    const float* lam   = (const float*)d_in[8];
    const float* asd   = (const float*)d_in[9];
    const float* w     = (const float*)d_in[10];
    const int*   cnt   = (const int*)d_in[11];
    float* out = (float*)d_out;

    cudaFuncSetAttribute(main_kernel, cudaFuncAttributeMaxDynamicSharedMemorySize,
                         SMEM_BYTES);

    k0_consts<<<1, 512>>>(stde, mu, sig, lam, asd, w, cnt);
    k1_proj<<<E, 128>>>(rot, dirs);
    main_kernel<<<NSM, 512, SMEM_BYTES>>>(alt, trans, rot);
    reduce_kernel<<<BV/4, 128>>>(out);
}

// round 5
// speedup vs baseline: 1.5690x; 1.5690x over previous
#include <cuda_runtime.h>
#include <cuda_bf16.h>
#include <math.h>
#include <stdint.h>
#include <string.h>

#define E   128
#define KC  12
#define BV  4096
#define RD  65536
#define NTILES (RD/128)
#define NSM 152

#define LOG2PI  1.8378770664093453f
#define SQRT2C  1.4142135623730951f
#define SQRTPI  1.7724538509055159f

// ---------------- device globals ----------------
__device__ float g_inv_std[E];
__device__ float g_sig2[E];
__device__ float g_sum_log_std;
__device__ float g_lsm[KC];
__device__ float g_kA[KC];
__device__ float g_kB[KC];
__device__ float g_kInvS[KC];
__device__ float g_kC[KC];
__device__ float g_kHL[KC];
__device__ float g_kOrthC[KC];
__device__ float g_kI2A[KC];
__device__ float g_P[E*KC];             // Rot^T @ unit_k, [e][k]
__device__ int   g_off[BV+1];
__device__ float g_scratch[(KC+1)*RD];  // [component][read]

// ---------------- helpers ----------------
__device__ __forceinline__ uint32_t smem_u32(const void* p){
    uint32_t a;
    asm("{ .reg .u64 t; cvta.to.shared.u64 t, %1; cvt.u32.u64 %0, t; }" : "=r"(a) : "l"(p));
    return a;
}
#define LDS128(r0,r1,r2,r3,addr) \
    asm volatile("ld.shared.v4.b32 {%0,%1,%2,%3}, [%4];" \
        : "=r"(r0),"=r"(r1),"=r"(r2),"=r"(r3) : "r"(addr))
#define LDS64(r0,r1,addr) \
    asm volatile("ld.shared.v2.b32 {%0,%1}, [%2];" : "=r"(r0),"=r"(r1) : "r"(addr))
#define STS32(addr,v) \
    asm volatile("st.shared.b32 [%0], %1;" :: "r"(addr), "r"(v))

__device__ __forceinline__ void mma_bf16(float* d, uint32_t a0, uint32_t a1,
                                         uint32_t a2, uint32_t a3,
                                         uint32_t b0, uint32_t b1){
    asm volatile("mma.sync.aligned.m16n8k16.row.col.f32.bf16.bf16.f32 "
        "{%0,%1,%2,%3}, {%4,%5,%6,%7}, {%8,%9}, {%0,%1,%2,%3};"
        : "+f"(d[0]), "+f"(d[1]), "+f"(d[2]), "+f"(d[3])
        : "r"(a0), "r"(a1), "r"(a2), "r"(a3), "r"(b0), "r"(b1));
}

// split a float pair into bf16 high + bf16 residual-low, packed as bf16x2 bits
__device__ __forceinline__ void split2(float v0, float v1, uint32_t& hb, uint32_t& lb){
    __nv_bfloat162 h = __float22bfloat162_rn(make_float2(v0, v1));
    float l0 = v0 - __bfloat162float(h.x);
    float l1 = v1 - __bfloat162float(h.y);
    __nv_bfloat162 lo = __float22bfloat162_rn(make_float2(l0, l1));
    memcpy(&hb, &h, 4);
    memcpy(&lb, &lo, 4);
}

// ---------------- K0: constants + prefix scan ----------------
__global__ void k0_consts(const float* __restrict__ stde,
                          const float* __restrict__ mu,
                          const float* __restrict__ sig,
                          const float* __restrict__ lam,
                          const float* __restrict__ asd,
                          const float* __restrict__ w,
                          const int*   __restrict__ counts)
{
    __shared__ float red[4];
    __shared__ int   wsum[16];
    const int t = threadIdx.x;
    const unsigned full = 0xffffffffu;

    float lv = 0.f;
    if (t < E){ float s = stde[t]; g_inv_std[t] = 1.f/s; g_sig2[t] = s*s; lv = logf(s); }
    for (int o=16;o>0;o>>=1) lv += __shfl_xor_sync(full, lv, o);
    if (t < E && (t&31)==0) red[t>>5] = lv;

    if (t < KC){
        float m=mu[t], s_=sig[t], l=lam[t], a=asd[t];
        float A = m + l*s_*s_;
        g_kA[t]    = A;
        g_kB[t]    = m + A;
        g_kInvS[t] = 1.f/(SQRT2C*s_);
        g_kC[t]    = logf(0.5f*l);
        g_kHL[t]   = 0.5f*l;
        g_kOrthC[t]= -0.5f*(float)(E-1)*LOG2PI - (float)(E-1)*logf(a);
        g_kI2A[t]  = 1.f/(2.f*a*a);
    }
    if (t==480){
        float mx = -1e30f;
        for (int k=0;k<KC;k++) mx = fmaxf(mx, w[k]);
        float s = 0.f;
        for (int k=0;k<KC;k++) s += expf(w[k]-mx);
        float lse = mx + logf(s);
        for (int k=0;k<KC;k++) g_lsm[k] = w[k] - lse;
    }
    __syncthreads();
    if (t==0) g_sum_log_std = red[0]+red[1]+red[2]+red[3];

    const int base = t*8;
    int c[8]; int s0 = 0;
    #pragma unroll
    for (int i=0;i<8;i++){ c[i] = counts[base+i]; s0 += c[i]; }
    int incl = s0;
    for (int o=1;o<32;o<<=1){
        int v = __shfl_up_sync(full, incl, o);
        if ((t&31) >= o) incl += v;
    }
    if ((t&31)==31) wsum[t>>5] = incl;
    __syncthreads();
    if (t==0){ int run=0; for (int i=0;i<16;i++){ int v=wsum[i]; wsum[i]=run; run+=v; } }
    __syncthreads();
    int run = wsum[t>>5] + incl - s0;
    #pragma unroll
    for (int i=0;i<8;i++){ g_off[base+i] = run; run += c[i]; }
    if (t==511) g_off[BV] = run;
}

// ---------------- K1: P = Rot^T @ unit ----------------
__global__ void k1_proj(const float* __restrict__ rot,
                        const float* __restrict__ dirs)
{
    __shared__ float rcol[E];
    const int e = blockIdx.x, t = threadIdx.x;
    const unsigned full = 0xffffffffu;
    rcol[t] = rot[t*E + e];
    __syncthreads();
    const int w = t>>5, l = t&31;
    #pragma unroll
    for (int kk=0; kk<3; kk++){
        int k = w*3 + kk;
        float ds = 0.f, ns = 0.f;
        #pragma unroll
        for (int j=l; j<E; j+=32){
            float d = dirs[k*E + j];
            ds = fmaf(rcol[j], d, ds);
            ns = fmaf(d, d, ns);
        }
        for (int o=16;o>0;o>>=1){
            ds += __shfl_xor_sync(full, ds, o);
            ns += __shfl_xor_sync(full, ns, o);
        }
        if (l==0) g_P[e*KC + k] = ds * rsqrtf(ns);
    }
}

// ---------------- K2: persistent HMMA GEMM + per-read log-liks ----------------
// fragment-major smem layouts (conflict-free LDS.128/LDS.64):
//   A frag:  [wm(8)][kb(8)][lane(32)] x 16B      = 32768 B (per buffer)
//   B frag:  [nb(18)][kb(8)][lane(32)] x 8B      = 36864 B (per buffer)
#define OFF_AH   0
#define OFF_AL   32768
#define OFF_BH   65536
#define OFF_BL   102400
#define OFF_DOT  139264   // [128][16] f32
#define OFF_S2B  147456   // [2][128] f32
#define OFF_NXB  148480   // [2][128] f32
#define OFF_SIG2 149504   // [128] f32
#define OFF_T    150016   // [128] f32
#define OFF_KON  150528   // 84 f32
#define SMEM_BYTES 151040

__global__ void __launch_bounds__(512,1)
main_kernel(const float* __restrict__ alt,
            const float* __restrict__ trans,
            const float* __restrict__ rot)
{
    extern __shared__ char sm[];
    const uint32_t smb = smem_u32(sm);
    const int tid = threadIdx.x, wid = tid>>5, lane = tid&31;
    float* SIG2f = (float*)(sm + OFF_SIG2);
    float* Tf    = (float*)(sm + OFF_T);
    float* KON   = (float*)(sm + OFF_KON);
    float* DOT   = (float*)(sm + OFF_DOT);
    float* S2B   = (float*)(sm + OFF_S2B);
    float* NXB   = (float*)(sm + OFF_NXB);

    if (tid < E){ Tf[tid] = trans[tid]; SIG2f[tid] = g_sig2[tid]; }
    if (tid < KC){
        KON[tid]    = g_kA[tid];    KON[12+tid] = g_kB[tid];
        KON[24+tid] = g_kInvS[tid]; KON[36+tid] = g_kC[tid];
        KON[48+tid] = g_kHL[tid];   KON[60+tid] = g_kOrthC[tid];
        KON[72+tid] = g_kI2A[tid];
    }

    // ---- B fill (once): rows 0..127 = Rot/sigma, 128..139 = P^T, 140..143 = 0
    for (int p = tid; p < 144*64; p += 512){
        int n = p>>6, k = (p&63)*2;
        float v0, v1;
        if (n < 128){
            float is = g_inv_std[n];
            v0 = rot[n*E+k]*is; v1 = rot[n*E+k+1]*is;
        } else if (n < 140){
            int kc = n-128;
            v0 = g_P[k*KC + kc]; v1 = g_P[(k+1)*KC + kc];
        } else { v0 = 0.f; v1 = 0.f; }
        uint32_t hb, lb;
        split2(v0, v1, hb, lb);
        int nb = n>>3;
        int l  = (n&7)*4 + ((k&7)>>1);
        int jB = (k>>3)&1;
        uint32_t byteB = (uint32_t)((nb*8 + (k>>4))*256 + l*8 + jB*4);
        STS32(smb + OFF_BH + byteB, hb);
        STS32(smb + OFF_BL + byteB, lb);
    }
    __syncthreads();

    const float slog = g_sum_log_std;
    const int wm = wid & 7, wcol = wid >> 3;
    const int lq = lane>>2, lr = lane&3;

    // conversion mapping for this thread
    const int cr = tid>>2, ck0 = (tid&3)*32;
    const int cwm = cr>>4, crho = cr&15;

    const uint32_t aAH = smb + OFF_AH + (uint32_t)(cwm*4096);
    const uint32_t aAL = smb + OFF_AL + (uint32_t)(cwm*4096);

    // MMA base addresses
    const uint32_t mAH = smb + OFF_AH + (uint32_t)(wm*4096 + lane*16);
    const uint32_t mAL = smb + OFF_AL + (uint32_t)(wm*4096 + lane*16);
    const uint32_t mBH = smb + OFF_BH + (uint32_t)(wcol*9*2048 + lane*8);
    const uint32_t mBL = smb + OFF_BL + (uint32_t)(wcol*9*2048 + lane*8);

    for (int tile = blockIdx.x; tile < NTILES; tile += gridDim.x){
        // ---- A conversion: a' = alt + t, split bf16, fragment-major store
        {
            const float* arow = alt + (size_t)(tile*128 + cr)*E + ck0;
            const float* trow = Tf + ck0;
            #pragma unroll
            for (int i=0;i<8;i++){
                float4 v = ((const float4*)arow)[i];
                float4 tv = ((const float4*)trow)[i];
                v.x += tv.x; v.y += tv.y; v.z += tv.z; v.w += tv.w;
                #pragma unroll
                for (int p2=0;p2<2;p2++){
                    int k = ck0 + 4*i + 2*p2;
                    float v0 = p2 ? v.z : v.x;
                    float v1 = p2 ? v.w : v.y;
                    uint32_t hb, lb;
                    split2(v0, v1, hb, lb);
                    int l  = (crho&7)*4 + ((k&7)>>1);
                    int jA = ((crho>>3)&1) + 2*((k>>3)&1);
                    uint32_t byteA = (uint32_t)((k>>4)*512 + l*16 + jA*4);
                    STS32(aAH + byteA, hb);
                    STS32(aAL + byteA, lb);
                }
            }
        }
        __syncthreads();

        // ---- MMA: 3 terms (ah*Bh, al*Bh, ah*Bl), K=128 each
        float acc[9][4];
        #pragma unroll
        for (int i=0;i<9;i++){ acc[i][0]=0.f; acc[i][1]=0.f; acc[i][2]=0.f; acc[i][3]=0.f; }

        const uint32_t Ab[3] = {mAH, mAL, mAH};
        const uint32_t Bb[3] = {mBH, mBH, mBL};
        #pragma unroll
        for (int t3=0; t3<3; t3++){
            #pragma unroll
            for (int kb=0; kb<8; kb++){
                uint32_t a0,a1,a2,a3;
                LDS128(a0,a1,a2,a3, Ab[t3] + kb*512);
                #pragma unroll
                for (int nb=0; nb<9; nb++){
                    uint32_t b0,b1;
                    LDS64(b0,b1, Bb[t3] + nb*2048 + kb*256);
                    mma_bf16(acc[nb], a0,a1,a2,a3, b0,b1);
                }
            }
        }

        // ---- extract: y-cols -> s2/nx partials, dot cols -> DOT
        const int r1 = wm*16 + lq, r2 = r1 + 8;
        float s2a=0.f, nxa=0.f, s2b=0.f, nxb=0.f;
        #pragma unroll
        for (int nb=0; nb<9; nb++){
            float c0=acc[nb][0], c1=acc[nb][1], c2=acc[nb][2], c3=acc[nb][3];
            if (wcol==0 || nb<7){
                int j0 = wcol*72 + nb*8 + 2*lr;
                float g0 = SIG2f[j0], g1 = SIG2f[j0+1];
                float q0=c0*c0, q1=c1*c1, q2=c2*c2, q3=c3*c3;
                s2a += q0+q1;  nxa = fmaf(q0,g0,fmaf(q1,g1,nxa));
                s2b += q2+q3;  nxb = fmaf(q2,g0,fmaf(q3,g1,nxb));
            } else {
                int kc = (nb-7)*8 + 2*lr;   // 0..15 (12..15 = pad)
                DOT[r1*16 + kc]   = c0;
                DOT[r1*16 + kc+1] = c1;
                DOT[r2*16 + kc]   = c2;
                DOT[r2*16 + kc+1] = c3;
            }
        }
        const unsigned full = 0xffffffffu;
        #pragma unroll
        for (int o=1;o<4;o<<=1){
            s2a += __shfl_xor_sync(full, s2a, o);
            nxa += __shfl_xor_sync(full, nxa, o);
            s2b += __shfl_xor_sync(full, s2b, o);
            nxb += __shfl_xor_sync(full, nxb, o);
        }
        if (lr==0){
            S2B[wcol*128 + r1] = s2a;  S2B[wcol*128 + r2] = s2b;
            NXB[wcol*128 + r1] = nxa;  NXB[wcol*128 + r2] = nxb;
        }
        __syncthreads();

        // ---- per-read epilogue: 4 threads/read, 3 clusters each
        {
            const int r = tid>>2, h = tid&3;
            const int gr = tile*128 + r;
            float s2 = S2B[r] + S2B[128+r];
            float nx = NXB[r] + NXB[128+r];
            if (h==0){
                float nonart = -64.f*LOG2PI - slog - 0.5f*s2;
                g_scratch[gr] = nonart;
            }
            #pragma unroll
            for (int kk=0; kk<3; kk++){
                int k = h*3 + kk;
                float dk    = DOT[r*16 + k];
                float orth2 = nx - dk*dk;
                float oll   = KON[60+k] - orth2*KON[72+k];
                float z     = (KON[k] - dk)*KON[24+k];
                float lec;
                if (z > 5.f){
                    float z2=z*z, z4=z2*z2, z6=z4*z2;
                    lec = -z2 - logf(z*SQRTPI)
                          + log1pf(-1.f/(2.f*z2) + 3.f/(4.f*z4) - 15.f/(8.f*z6));
                } else {
                    lec = logf(erfcf(z));
                }
                float par = KON[36+k] + lec + KON[48+k]*(KON[12+k] - 2.f*dk);
                g_scratch[(size_t)(1+k)*RD + gr] = oll + par;
            }
        }
        __syncthreads();
    }
}

// ---------------- K3: warp-per-variant segment sums + logits ----------------
__global__ void reduce_kernel(float* __restrict__ out)
{
    const int b    = blockIdx.x*8 + (threadIdx.x>>5);
    const int lane = threadIdx.x & 31;
    const unsigned full = 0xffffffffu;
    const int lo = g_off[b], hi = g_off[b+1];

    float v = -1e30f, nonart = 0.f;
    #pragma unroll
    for (int c=0; c<KC+1; c++){
        float p = 0.f;
        for (int r = lo + lane; r < hi; r += 32)
            p += g_scratch[(size_t)c*RD + r];
        #pragma unroll
        for (int o=16;o>0;o>>=1) p += __shfl_xor_sync(full, p, o);
        if (c==0) nonart = p;
        if (lane==c) v = (c==0) ? p : p + g_lsm[c-1];
    }
    float m = (lane>=1 && lane<KC+1) ? v : -1e30f;
    for (int o=16;o>0;o>>=1) m = fmaxf(m, __shfl_xor_sync(full, m, o));
    float e = (lane>=1 && lane<KC+1) ? expf(v-m) : 0.f;
    for (int o=16;o>0;o>>=1) e += __shfl_xor_sync(full, e, o);
    float lse = m + logf(e);
    float logits = lse - nonart;

    if (lane==0)     out[b] = 20.f*tanhf(logits*(1.f/20.f));
    if (lane<KC+1)   out[BV + b*(KC+1) + lane] = v;
}

// ---------------- launch ----------------
extern "C" void kernel_launch(void* const* d_in, const int* in_sizes, int n_in,
                              void* d_out, int out_size)
{
    const float* alt   = (const float*)d_in[0];
    // d_in[1] = ref_re: unused by the reference output
    const float* trans = (const float*)d_in[2];
    const float* rot   = (const float*)d_in[3];
    const float* stde  = (const float*)d_in[4];
    const float* dirs  = (const float*)d_in[5];
    const float* mu    = (const float*)d_in[6];
    const float* sig   = (const float*)d_in[7];
    const float* lam   = (const float*)d_in[8];
    const float* asd   = (const float*)d_in[9];
    const float* w     = (const float*)d_in[10];
    const int*   cnt   = (const int*)d_in[11];
    float* out = (float*)d_out;

    cudaFuncSetAttribute(main_kernel, cudaFuncAttributeMaxDynamicSharedMemorySize,
                         SMEM_BYTES);

    k0_consts<<<1, 512>>>(stde, mu, sig, lam, asd, w, cnt);
    k1_proj<<<E, 128>>>(rot, dirs);
    main_kernel<<<NSM, 512, SMEM_BYTES>>>(alt, trans, rot);
    reduce_kernel<<<BV/8, 256>>>(out);
}

// round 6
// speedup vs baseline: 2.6112x; 1.6642x over previous
#include <cuda_runtime.h>
#include <cuda_bf16.h>
#include <math.h>
#include <stdint.h>
#include <string.h>

#define E   128
#define KC  12
#define BV  4096
#define RD  65536
#define NTILES (RD/128)
#define NUNITS (NTILES/2)
#define NSM 152

#define LOG2PI  1.8378770664093453f
#define SQRT2C  1.4142135623730951f
#define SQRTPI  1.7724538509055159f

// ---------------- device globals ----------------
__device__ float g_inv_std[E];
__device__ float g_sig2[E];
__device__ float g_sum_log_std;
__device__ float g_lsm[KC];
__device__ float g_kA[KC];
__device__ float g_kB[KC];
__device__ float g_kInvS[KC];
__device__ float g_kC[KC];
__device__ float g_kHL[KC];
__device__ float g_kOrthC[KC];
__device__ float g_kI2A[KC];
__device__ float g_P[E*KC];             // Rot^T @ unit_k, [e][k]
__device__ int   g_off[BV+1];
__device__ float g_scratch[(KC+1)*RD];  // [component][read]

// ---------------- helpers ----------------
__device__ __forceinline__ uint32_t smem_u32(const void* p){
    uint32_t a;
    asm("{ .reg .u64 t; cvta.to.shared.u64 t, %1; cvt.u32.u64 %0, t; }" : "=r"(a) : "l"(p));
    return a;
}
#define LDS128(r0,r1,r2,r3,addr) \
    asm volatile("ld.shared.v4.b32 {%0,%1,%2,%3}, [%4];" \
        : "=r"(r0),"=r"(r1),"=r"(r2),"=r"(r3) : "r"(addr))
#define LDS64(r0,r1,addr) \
    asm volatile("ld.shared.v2.b32 {%0,%1}, [%2];" : "=r"(r0),"=r"(r1) : "r"(addr))
#define STS32(addr,v) \
    asm volatile("st.shared.b32 [%0], %1;" :: "r"(addr), "r"(v))
#define STS64F(addr,v0,v1) \
    asm volatile("st.shared.v2.f32 [%0], {%1,%2};" :: "r"(addr), "f"(v0), "f"(v1))
#define STS128(addr,r0,r1,r2,r3) \
    asm volatile("st.shared.v4.b32 [%0], {%1,%2,%3,%4};" \
        :: "r"(addr), "r"(r0),"r"(r1),"r"(r2),"r"(r3))

__device__ __forceinline__ void mma_bf16(float* d, uint32_t a0, uint32_t a1,
                                         uint32_t a2, uint32_t a3,
                                         uint32_t b0, uint32_t b1){
    asm("mma.sync.aligned.m16n8k16.row.col.f32.bf16.bf16.f32 "
        "{%0,%1,%2,%3}, {%4,%5,%6,%7}, {%8,%9}, {%0,%1,%2,%3};"
        : "+f"(d[0]), "+f"(d[1]), "+f"(d[2]), "+f"(d[3])
        : "r"(a0), "r"(a1), "r"(a2), "r"(a3), "r"(b0), "r"(b1));
}

__device__ __forceinline__ void split2(float v0, float v1, uint32_t& hb, uint32_t& lb){
    __nv_bfloat162 h = __float22bfloat162_rn(make_float2(v0, v1));
    float l0 = v0 - __bfloat162float(h.x);
    float l1 = v1 - __bfloat162float(h.y);
    __nv_bfloat162 lo = __float22bfloat162_rn(make_float2(l0, l1));
    memcpy(&hb, &h, 4);
    memcpy(&lb, &lo, 4);
}

// ---------------- K0: constants + prefix scan ----------------
__global__ void k0_consts(const float* __restrict__ stde,
                          const float* __restrict__ mu,
                          const float* __restrict__ sig,
                          const float* __restrict__ lam,
                          const float* __restrict__ asd,
                          const float* __restrict__ w,
                          const int*   __restrict__ counts)
{
    __shared__ float red[4];
    __shared__ int   wsum[16];
    const int t = threadIdx.x;
    const unsigned full = 0xffffffffu;

    float lv = 0.f;
    if (t < E){ float s = stde[t]; g_inv_std[t] = 1.f/s; g_sig2[t] = s*s; lv = logf(s); }
    for (int o=16;o>0;o>>=1) lv += __shfl_xor_sync(full, lv, o);
    if (t < E && (t&31)==0) red[t>>5] = lv;

    if (t < KC){
        float m=mu[t], s_=sig[t], l=lam[t], a=asd[t];
        float A = m + l*s_*s_;
        g_kA[t]    = A;
        g_kB[t]    = m + A;
        g_kInvS[t] = 1.f/(SQRT2C*s_);
        g_kC[t]    = logf(0.5f*l);
        g_kHL[t]   = 0.5f*l;
        g_kOrthC[t]= -0.5f*(float)(E-1)*LOG2PI - (float)(E-1)*logf(a);
        g_kI2A[t]  = 1.f/(2.f*a*a);
    }
    if (t==480){
        float mx = -1e30f;
        for (int k=0;k<KC;k++) mx = fmaxf(mx, w[k]);
        float s = 0.f;
        for (int k=0;k<KC;k++) s += expf(w[k]-mx);
        float lse = mx + logf(s);
        for (int k=0;k<KC;k++) g_lsm[k] = w[k] - lse;
    }
    __syncthreads();
    if (t==0) g_sum_log_std = red[0]+red[1]+red[2]+red[3];

    const int base = t*8;
    int c[8]; int s0 = 0;
    #pragma unroll
    for (int i=0;i<8;i++){ c[i] = counts[base+i]; s0 += c[i]; }
    int incl = s0;
    for (int o=1;o<32;o<<=1){
        int v = __shfl_up_sync(full, incl, o);
        if ((t&31) >= o) incl += v;
    }
    if ((t&31)==31) wsum[t>>5] = incl;
    __syncthreads();
    if (t==0){ int run=0; for (int i=0;i<16;i++){ int v=wsum[i]; wsum[i]=run; run+=v; } }
    __syncthreads();
    int run = wsum[t>>5] + incl - s0;
    #pragma unroll
    for (int i=0;i<8;i++){ g_off[base+i] = run; run += c[i]; }
    if (t==511) g_off[BV] = run;
}

// ---------------- K1: P = Rot^T @ unit ----------------
__global__ void k1_proj(const float* __restrict__ rot,
                        const float* __restrict__ dirs)
{
    __shared__ float rcol[E];
    const int e = blockIdx.x, t = threadIdx.x;
    const unsigned full = 0xffffffffu;
    rcol[t] = rot[t*E + e];
    __syncthreads();
    const int w = t>>5, l = t&31;
    #pragma unroll
    for (int kk=0; kk<3; kk++){
        int k = w*3 + kk;
        float ds = 0.f, ns = 0.f;
        #pragma unroll
        for (int j=l; j<E; j+=32){
            float d = dirs[k*E + j];
            ds = fmaf(rcol[j], d, ds);
            ns = fmaf(d, d, ns);
        }
        for (int o=16;o>0;o>>=1){
            ds += __shfl_xor_sync(full, ds, o);
            ns += __shfl_xor_sync(full, ns, o);
        }
        if (l==0) g_P[e*KC + k] = ds * rsqrtf(ns);
    }
}

// ---------------- K2: persistent HMMA, 2 tiles/iter, M32 per warp ----------------
// A frag: per tile per buffer: [strip*2+sub (8)][kb(8)][lane(32)] x 16B = 32KB
// B frag: [nb(18)][kb(8)][lane(32)] x 8B = 36864B per buffer
#define OFF_AH   0         // 2 x 32768
#define OFF_AL   65536     // 2 x 32768
#define OFF_BH   131072    // 36864
#define OFF_BL   167936    // 36864
#define OFF_DOT  204800    // [2][128][12] f32 = 12288
#define OFF_S2B  217088    // [2][2][128] f32 = 4096
#define OFF_NXB  221184    // 4096
#define OFF_SIG2 225280    // 512
#define OFF_T    225792    // 512
#define OFF_KON  226304    // 336
#define SMEM_BYTES 226688

__global__ void __launch_bounds__(512,1)
main_kernel(const float* __restrict__ alt,
            const float* __restrict__ trans,
            const float* __restrict__ rot)
{
    extern __shared__ char sm[];
    const uint32_t smb = smem_u32(sm);
    const int tid = threadIdx.x, wid = tid>>5, lane = tid&31;
    const int lq = lane>>2, lr = lane&3;
    float* SIG2f = (float*)(sm + OFF_SIG2);
    float* Tf    = (float*)(sm + OFF_T);
    float* KON   = (float*)(sm + OFF_KON);
    float* DOTf  = (float*)(sm + OFF_DOT);
    float* S2Bf  = (float*)(sm + OFF_S2B);
    float* NXBf  = (float*)(sm + OFF_NXB);

    if (tid < E){ Tf[tid] = trans[tid]; SIG2f[tid] = g_sig2[tid]; }
    if (tid < KC){
        KON[tid]    = g_kA[tid];    KON[12+tid] = g_kB[tid];
        KON[24+tid] = g_kInvS[tid]; KON[36+tid] = g_kC[tid];
        KON[48+tid] = g_kHL[tid];   KON[60+tid] = g_kOrthC[tid];
        KON[72+tid] = g_kI2A[tid];
    }

    // ---- B fill (once): rows 0..127 = Rot/sigma, 128..139 = P^T, 140..143 = 0
    for (int p = tid; p < 144*64; p += 512){
        int n = p>>6, k = (p&63)*2;
        float v0, v1;
        if (n < 128){
            float is = g_inv_std[n];
            v0 = rot[n*E+k]*is; v1 = rot[n*E+k+1]*is;
        } else if (n < 140){
            int kc = n-128;
            v0 = g_P[k*KC + kc]; v1 = g_P[(k+1)*KC + kc];
        } else { v0 = 0.f; v1 = 0.f; }
        uint32_t hb, lb;
        split2(v0, v1, hb, lb);
        int nb = n>>3;
        int l  = (n&7)*4 + ((k&7)>>1);
        int jB = (k>>3)&1;
        uint32_t byteB = (uint32_t)((nb*8 + (k>>4))*256 + l*8 + jB*4);
        STS32(smb + OFF_BH + byteB, hb);
        STS32(smb + OFF_BL + byteB, lb);
    }

    const float slog = g_sum_log_std;

    // conversion mapping: warp -> (tile tt, strip cs, sub csub); lane -> (lq,lr)
    const int tt = wid>>3, cs = (wid&7)>>1, csub = wid&1;
    const uint32_t convBase = smb + (uint32_t)(tt*32768 + ((cs*2+csub)*8)*512 + lane*16);

    // MMA mapping: warp -> (tile tm, strip ms, half hf)
    const int tm = wid>>3, ms = wid&3, hf = (wid>>2)&1;
    const uint32_t aBase = smb + (uint32_t)(tm*32768 + (ms*2)*8*512 + lane*16);
    const uint32_t bhBase = smb + OFF_BH + (uint32_t)((hf*9*8)*256 + lane*8);
    const uint32_t blBase = smb + OFF_BL + (uint32_t)((hf*9*8)*256 + lane*8);

    const float2* a2 = (const float2*)alt;

    // ---- conversion: gather exact fragments, 2 conflict-free STS128 per chunk
    auto convert = [&](int unit){
        const int row0 = (unit*2 + tt)*128 + cs*32 + csub*16 + lq;
        #pragma unroll
        for (int kb=0; kb<8; kb++){
            int c0 = kb*16 + 2*lr, c1 = c0 + 8;
            float2 v00 = a2[(size_t)row0*64     + (c0>>1)];
            float2 v10 = a2[(size_t)(row0+8)*64 + (c0>>1)];
            float2 v01 = a2[(size_t)row0*64     + (c1>>1)];
            float2 v11 = a2[(size_t)(row0+8)*64 + (c1>>1)];
            float2 t0 = *(const float2*)(Tf + c0);
            float2 t1 = *(const float2*)(Tf + c1);
            uint32_t h0,l0,h1,l1,h2,l2,h3,l3;
            split2(v00.x+t0.x, v00.y+t0.y, h0, l0);
            split2(v10.x+t0.x, v10.y+t0.y, h1, l1);
            split2(v01.x+t1.x, v01.y+t1.y, h2, l2);
            split2(v11.x+t1.x, v11.y+t1.y, h3, l3);
            STS128(convBase + kb*512,           h0,h1,h2,h3);
            STS128(convBase + OFF_AL + kb*512,  l0,l1,l2,l3);
        }
    };

    int u = blockIdx.x;
    if (u < NUNITS) convert(u);

    while (u < NUNITS){
        __syncthreads();   // conversion visible; prev DOT consumed

        // ---- MMA: 3 terms, 2 m16-frags per warp (rows ms*32..+31)
        float acc0[9][4], acc1[9][4];
        #pragma unroll
        for (int i=0;i<9;i++){
            acc0[i][0]=0.f;acc0[i][1]=0.f;acc0[i][2]=0.f;acc0[i][3]=0.f;
            acc1[i][0]=0.f;acc1[i][1]=0.f;acc1[i][2]=0.f;acc1[i][3]=0.f;
        }
        #pragma unroll
        for (int kb=0; kb<8; kb++){
            uint32_t ah0[4], ah1[4], al0[4], al1[4];
            LDS128(ah0[0],ah0[1],ah0[2],ah0[3], aBase + kb*512);
            LDS128(ah1[0],ah1[1],ah1[2],ah1[3], aBase + 4096 + kb*512);
            LDS128(al0[0],al0[1],al0[2],al0[3], aBase + OFF_AL + kb*512);
            LDS128(al1[0],al1[1],al1[2],al1[3], aBase + OFF_AL + 4096 + kb*512);
            #pragma unroll
            for (int nb=0; nb<9; nb++){
                uint32_t bh0,bh1,bl0,bl1;
                LDS64(bh0,bh1, bhBase + (nb*8+kb)*256);
                LDS64(bl0,bl1, blBase + (nb*8+kb)*256);
                mma_bf16(acc0[nb], ah0[0],ah0[1],ah0[2],ah0[3], bh0,bh1);
                mma_bf16(acc1[nb], ah1[0],ah1[1],ah1[2],ah1[3], bh0,bh1);
                mma_bf16(acc0[nb], al0[0],al0[1],al0[2],al0[3], bh0,bh1);
                mma_bf16(acc1[nb], al1[0],al1[1],al1[2],al1[3], bh0,bh1);
                mma_bf16(acc0[nb], ah0[0],ah0[1],ah0[2],ah0[3], bl0,bl1);
                mma_bf16(acc1[nb], ah1[0],ah1[1],ah1[2],ah1[3], bl0,bl1);
            }
        }

        // ---- extract: s2/nx partials + dot columns
        float s2v[4]={0.f,0.f,0.f,0.f}, nxv[4]={0.f,0.f,0.f,0.f};
        #pragma unroll
        for (int nb=0; nb<9; nb++){
            int col = hf*72 + nb*8 + 2*lr;
            if (hf==0 || nb<7){
                float g0 = SIG2f[col], g1 = SIG2f[col+1];
                float q;
                q = acc0[nb][0]*acc0[nb][0]; s2v[0]+=q; nxv[0]=fmaf(q,g0,nxv[0]);
                q = acc0[nb][1]*acc0[nb][1]; s2v[0]+=q; nxv[0]=fmaf(q,g1,nxv[0]);
                q = acc0[nb][2]*acc0[nb][2]; s2v[1]+=q; nxv[1]=fmaf(q,g0,nxv[1]);
                q = acc0[nb][3]*acc0[nb][3]; s2v[1]+=q; nxv[1]=fmaf(q,g1,nxv[1]);
                q = acc1[nb][0]*acc1[nb][0]; s2v[2]+=q; nxv[2]=fmaf(q,g0,nxv[2]);
                q = acc1[nb][1]*acc1[nb][1]; s2v[2]+=q; nxv[2]=fmaf(q,g1,nxv[2]);
                q = acc1[nb][2]*acc1[nb][2]; s2v[3]+=q; nxv[3]=fmaf(q,g0,nxv[3]);
                q = acc1[nb][3]*acc1[nb][3]; s2v[3]+=q; nxv[3]=fmaf(q,g1,nxv[3]);
            } else {
                int kc = (nb-7)*8 + 2*lr;
                if (kc < 12){
                    int r0 = ms*32 + lq;
                    uint32_t dbase = smb + OFF_DOT + (uint32_t)(tm*128*48);
                    STS64F(dbase + (uint32_t)((r0   )*48 + kc*4), acc0[nb][0], acc0[nb][1]);
                    STS64F(dbase + (uint32_t)((r0+ 8)*48 + kc*4), acc0[nb][2], acc0[nb][3]);
                    STS64F(dbase + (uint32_t)((r0+16)*48 + kc*4), acc1[nb][0], acc1[nb][1]);
                    STS64F(dbase + (uint32_t)((r0+24)*48 + kc*4), acc1[nb][2], acc1[nb][3]);
                }
            }
        }
        const unsigned full = 0xffffffffu;
        #pragma unroll
        for (int o=1;o<4;o<<=1){
            #pragma unroll
            for (int i=0;i<4;i++){
                s2v[i] += __shfl_xor_sync(full, s2v[i], o);
                nxv[i] += __shfl_xor_sync(full, nxv[i], o);
            }
        }
        {
            float sv = (lr==0)?s2v[0]:(lr==1)?s2v[1]:(lr==2)?s2v[2]:s2v[3];
            float nv = (lr==0)?nxv[0]:(lr==1)?nxv[1]:(lr==2)?nxv[2]:nxv[3];
            int row = ms*32 + lr*8 + lq;
            S2Bf[(tm*2+hf)*128 + row] = sv;
            NXBf[(tm*2+hf)*128 + row] = nv;
        }
        __syncthreads();   // DOT/S2B/NXB ready; A frags free

        int un = u + gridDim.x;
        if (un < NUNITS) convert(un);   // LDG issues early, overlaps epilogue

        // ---- epilogue: 2 threads per read, 6 clusters each
        {
            const int r = tid>>1, h = tid&1;
            const int te = r>>7, rl = r&127;
            const int gr = (u*2 + te)*128 + rl;
            float s2 = S2Bf[(te*2)*128 + rl] + S2Bf[(te*2+1)*128 + rl];
            float nx = NXBf[(te*2)*128 + rl] + NXBf[(te*2+1)*128 + rl];
            if (h==0)
                g_scratch[gr] = -64.f*LOG2PI - slog - 0.5f*s2;
            const float* drow = DOTf + te*128*12 + rl*12;
            #pragma unroll
            for (int kk=0; kk<6; kk++){
                int k = h*6 + kk;
                float dk    = drow[k];
                float orth2 = nx - dk*dk;
                float oll   = KON[60+k] - orth2*KON[72+k];
                float z     = (KON[k] - dk)*KON[24+k];
                float lec;
                if (z > 5.f){
                    float z2=z*z, z4=z2*z2, z6=z4*z2;
                    lec = -z2 - logf(z*SQRTPI)
                          + log1pf(-1.f/(2.f*z2) + 3.f/(4.f*z4) - 15.f/(8.f*z6));
                } else {
                    lec = logf(erfcf(z));
                }
                float par = KON[36+k] + lec + KON[48+k]*(KON[12+k] - 2.f*dk);
                g_scratch[(size_t)(1+k)*RD + gr] = oll + par;
            }
        }
        u = un;
    }
}

// ---------------- K3: 2 variants per warp, lane = read ----------------
__global__ void reduce_kernel(float* __restrict__ out)
{
    const int lane = threadIdx.x & 31;
    const int vsel = lane>>4, rr = lane&15;
    const int b = blockIdx.x*16 + (threadIdx.x>>5)*2 + vsel;
    const unsigned full = 0xffffffffu;
    const int lo = g_off[b], hi = g_off[b+1];

    float comp = 0.f;
    #pragma unroll
    for (int c=0; c<KC+1; c++){
        float p = 0.f;
        for (int rd = lo + rr; rd < hi; rd += 16)
            p += g_scratch[(size_t)c*RD + rd];
        p += __shfl_xor_sync(full, p, 8);
        p += __shfl_xor_sync(full, p, 4);
        p += __shfl_xor_sync(full, p, 2);
        p += __shfl_xor_sync(full, p, 1);
        if (rr == c) comp = p;
    }
    float nonart = __shfl_sync(full, comp, lane & 16);
    bool isart = (rr >= 1 && rr <= KC);
    float v = comp + (isart ? g_lsm[rr-1] : 0.f);
    float m = isart ? v : -1e30f;
    for (int o=8;o>0;o>>=1) m = fmaxf(m, __shfl_xor_sync(full, m, o));
    float e = isart ? expf(v-m) : 0.f;
    for (int o=8;o>0;o>>=1) e += __shfl_xor_sync(full, e, o);
    float logits = m + logf(e) - nonart;

    if (rr==0)      out[b] = 20.f*tanhf(logits*(1.f/20.f));
    if (rr<=KC)     out[BV + b*(KC+1) + rr] = v;
}

// ---------------- launch ----------------
extern "C" void kernel_launch(void* const* d_in, const int* in_sizes, int n_in,
                              void* d_out, int out_size)
{
    const float* alt   = (const float*)d_in[0];
    // d_in[1] = ref_re: unused by the reference output
    const float* trans = (const float*)d_in[2];
    const float* rot   = (const float*)d_in[3];
    const float* stde  = (const float*)d_in[4];
    const float* dirs  = (const float*)d_in[5];
    const float* mu    = (const float*)d_in[6];
    const float* sig   = (const float*)d_in[7];
    const float* lam   = (const float*)d_in[8];
    const float* asd   = (const float*)d_in[9];
    const float* w     = (const float*)d_in[10];
    const int*   cnt   = (const int*)d_in[11];
    float* out = (float*)d_out;

    cudaFuncSetAttribute(main_kernel, cudaFuncAttributeMaxDynamicSharedMemorySize,
                         SMEM_BYTES);

    k0_consts<<<1, 512>>>(stde, mu, sig, lam, asd, w, cnt);
    k1_proj<<<E, 128>>>(rot, dirs);
    main_kernel<<<NSM, 512, SMEM_BYTES>>>(alt, trans, rot);
    reduce_kernel<<<BV/16, 256>>>(out);
}

// round 7
// speedup vs baseline: 2.9782x; 1.1405x over previous
#include <cuda_runtime.h>
#include <cuda_bf16.h>
#include <math.h>
#include <stdint.h>
#include <string.h>

#define E   128
#define KC  12
#define BV  4096
#define RD  65536
#define NTILES (RD/128)
#define NUNITS (NTILES/2)
#define GRID_MAIN 128

#define LOG2PI  1.8378770664093453f
#define SQRT2C  1.4142135623730951f
#define SQRTPI  1.7724538509055159f

// ---------------- device globals ----------------
__device__ float g_inv_std[E];
__device__ float g_sig2[E];
__device__ float g_sum_log_std;
__device__ float g_lsm[KC];
__device__ float g_kA[KC];
__device__ float g_kB[KC];
__device__ float g_kInvS[KC];
__device__ float g_kC[KC];
__device__ float g_kHL[KC];
__device__ float g_kOrthC[KC];
__device__ float g_kI2A[KC];
__device__ float g_P[E*KC];             // Rot^T @ unit_k, [e][k]
__device__ int   g_off[BV+1];
__device__ float g_scratch[(KC+1)*RD];  // [component][read]

// ---------------- helpers ----------------
__device__ __forceinline__ uint32_t smem_u32(const void* p){
    uint32_t a;
    asm("{ .reg .u64 t; cvta.to.shared.u64 t, %1; cvt.u32.u64 %0, t; }" : "=r"(a) : "l"(p));
    return a;
}
#define LDS128(r0,r1,r2,r3,addr) \
    asm volatile("ld.shared.v4.b32 {%0,%1,%2,%3}, [%4];" \
        : "=r"(r0),"=r"(r1),"=r"(r2),"=r"(r3) : "r"(addr))
#define LDS64(r0,r1,addr) \
    asm volatile("ld.shared.v2.b32 {%0,%1}, [%2];" : "=r"(r0),"=r"(r1) : "r"(addr))
#define STS32(addr,v) \
    asm volatile("st.shared.b32 [%0], %1;" :: "r"(addr), "r"(v))
#define STS64F(addr,v0,v1) \
    asm volatile("st.shared.v2.f32 [%0], {%1,%2};" :: "r"(addr), "f"(v0), "f"(v1))
#define STS128(addr,r0,r1,r2,r3) \
    asm volatile("st.shared.v4.b32 [%0], {%1,%2,%3,%4};" \
        :: "r"(addr), "r"(r0),"r"(r1),"r"(r2),"r"(r3))

__device__ __forceinline__ void mma_bf16(float* d, uint32_t a0, uint32_t a1,
                                         uint32_t a2, uint32_t a3,
                                         uint32_t b0, uint32_t b1){
    asm("mma.sync.aligned.m16n8k16.row.col.f32.bf16.bf16.f32 "
        "{%0,%1,%2,%3}, {%4,%5,%6,%7}, {%8,%9}, {%0,%1,%2,%3};"
        : "+f"(d[0]), "+f"(d[1]), "+f"(d[2]), "+f"(d[3])
        : "r"(a0), "r"(a1), "r"(a2), "r"(a3), "r"(b0), "r"(b1));
}

__device__ __forceinline__ void split2(float v0, float v1, uint32_t& hb, uint32_t& lb){
    __nv_bfloat162 h = __float22bfloat162_rn(make_float2(v0, v1));
    float l0 = v0 - __bfloat162float(h.x);
    float l1 = v1 - __bfloat162float(h.y);
    __nv_bfloat162 lo = __float22bfloat162_rn(make_float2(l0, l1));
    memcpy(&hb, &h, 4);
    memcpy(&lb, &lo, 4);
}

// ---------------- K01: merged constants + prefix scan + projections ----------------
// blocks 0..127: P[e][k] column for e = blockIdx.x;  block 128: scalar consts + scan
__global__ void __launch_bounds__(512,1)
k01_setup(const float* __restrict__ rot,
          const float* __restrict__ dirs,
          const float* __restrict__ stde,
          const float* __restrict__ mu,
          const float* __restrict__ sig,
          const float* __restrict__ lam,
          const float* __restrict__ asd,
          const float* __restrict__ w,
          const int*   __restrict__ counts)
{
    const int t = threadIdx.x;
    const unsigned full = 0xffffffffu;

    if (blockIdx.x < 128){
        // ---- k1: P = Rot^T @ unit for column e
        __shared__ float rcol[E];
        const int e = blockIdx.x;
        if (t < E) rcol[t] = rot[t*E + e];
        __syncthreads();
        const int wd = t>>5, l = t&31;
        if (wd < KC){
            int k = wd;
            float ds = 0.f, ns = 0.f;
            #pragma unroll
            for (int j=l; j<E; j+=32){
                float d = dirs[k*E + j];
                ds = fmaf(rcol[j], d, ds);
                ns = fmaf(d, d, ns);
            }
            #pragma unroll
            for (int o=16;o>0;o>>=1){
                ds += __shfl_xor_sync(full, ds, o);
                ns += __shfl_xor_sync(full, ns, o);
            }
            if (l==0) g_P[e*KC + k] = ds * rsqrtf(ns);
        }
        return;
    }

    // ---- k0: constants
    __shared__ float red[4];
    __shared__ int   wsum[16];

    float lv = 0.f;
    if (t < E){ float s = stde[t]; g_inv_std[t] = 1.f/s; g_sig2[t] = s*s; lv = logf(s); }
    #pragma unroll
    for (int o=16;o>0;o>>=1) lv += __shfl_xor_sync(full, lv, o);
    if (t < E && (t&31)==0) red[t>>5] = lv;

    if (t < KC){
        float m=mu[t], s_=sig[t], l=lam[t], a=asd[t];
        float A = m + l*s_*s_;
        g_kA[t]    = A;
        g_kB[t]    = m + A;
        g_kInvS[t] = 1.f/(SQRT2C*s_);
        g_kC[t]    = logf(0.5f*l);
        g_kHL[t]   = 0.5f*l;
        g_kOrthC[t]= -0.5f*(float)(E-1)*LOG2PI - (float)(E-1)*logf(a);
        g_kI2A[t]  = 1.f/(2.f*a*a);
    }
    // log-softmax via warp butterfly (lanes 0..15 valid space, 12 used)
    if (t < 32){
        float v = (t < KC) ? w[t] : -1e30f;
        float m = v;
        #pragma unroll
        for (int o=8;o>0;o>>=1) m = fmaxf(m, __shfl_xor_sync(full, m, o));
        float e = (t < KC) ? expf(v-m) : 0.f;
        #pragma unroll
        for (int o=8;o>0;o>>=1) e += __shfl_xor_sync(full, e, o);
        if (t < KC) g_lsm[t] = v - (m + logf(e));
    }
    __syncthreads();
    if (t==0) g_sum_log_std = red[0]+red[1]+red[2]+red[3];

    // prefix scan of counts (512 x 8)
    const int base = t*8;
    int c[8]; int s0 = 0;
    #pragma unroll
    for (int i=0;i<8;i++){ c[i] = counts[base+i]; s0 += c[i]; }
    int incl = s0;
    #pragma unroll
    for (int o=1;o<32;o<<=1){
        int v = __shfl_up_sync(full, incl, o);
        if ((t&31) >= o) incl += v;
    }
    if ((t&31)==31) wsum[t>>5] = incl;
    __syncthreads();
    if (t==0){ int run=0; for (int i=0;i<16;i++){ int v=wsum[i]; wsum[i]=run; run+=v; } }
    __syncthreads();
    int run = wsum[t>>5] + incl - s0;
    #pragma unroll
    for (int i=0;i<8;i++){ g_off[base+i] = run; run += c[i]; }
    if (t==511) g_off[BV] = run;
}

// ---------------- K2: persistent HMMA, 2 tiles/iter, M32 per warp ----------------
#define OFF_AH   0         // 2 x 32768
#define OFF_AL   65536     // 2 x 32768
#define OFF_BH   131072    // 36864
#define OFF_BL   167936    // 36864
#define OFF_DOT  204800    // [2][128][12] f32 = 12288
#define OFF_S2B  217088    // [2][2][128] f32 = 4096
#define OFF_NXB  221184    // 4096
#define OFF_SIG2 225280    // 512
#define OFF_T    225792    // 512
#define OFF_KON  226304    // 336
#define SMEM_BYTES 226688

__global__ void __launch_bounds__(512,1)
main_kernel(const float* __restrict__ alt,
            const float* __restrict__ trans,
            const float* __restrict__ rot)
{
    extern __shared__ char sm[];
    const uint32_t smb = smem_u32(sm);
    const int tid = threadIdx.x, wid = tid>>5, lane = tid&31;
    const int lq = lane>>2, lr = lane&3;
    float* SIG2f = (float*)(sm + OFF_SIG2);
    float* Tf    = (float*)(sm + OFF_T);
    float* KON   = (float*)(sm + OFF_KON);
    float* DOTf  = (float*)(sm + OFF_DOT);
    float* S2Bf  = (float*)(sm + OFF_S2B);
    float* NXBf  = (float*)(sm + OFF_NXB);

    if (tid < E){ Tf[tid] = trans[tid]; SIG2f[tid] = g_sig2[tid]; }
    if (tid < KC){
        KON[tid]    = g_kA[tid];    KON[12+tid] = g_kB[tid];
        KON[24+tid] = g_kInvS[tid]; KON[36+tid] = g_kC[tid];
        KON[48+tid] = g_kHL[tid];   KON[60+tid] = g_kOrthC[tid];
        KON[72+tid] = g_kI2A[tid];
    }

    // ---- B fill (once): rows 0..127 = Rot/sigma, 128..139 = P^T, 140..143 = 0
    for (int p = tid; p < 144*64; p += 512){
        int n = p>>6, k = (p&63)*2;
        float v0, v1;
        if (n < 128){
            float is = g_inv_std[n];
            v0 = rot[n*E+k]*is; v1 = rot[n*E+k+1]*is;
        } else if (n < 140){
            int kc = n-128;
            v0 = g_P[k*KC + kc]; v1 = g_P[(k+1)*KC + kc];
        } else { v0 = 0.f; v1 = 0.f; }
        uint32_t hb, lb;
        split2(v0, v1, hb, lb);
        int nb = n>>3;
        int l  = (n&7)*4 + ((k&7)>>1);
        int jB = (k>>3)&1;
        uint32_t byteB = (uint32_t)((nb*8 + (k>>4))*256 + l*8 + jB*4);
        STS32(smb + OFF_BH + byteB, hb);
        STS32(smb + OFF_BL + byteB, lb);
    }

    const float slog = g_sum_log_std;

    // conversion mapping: warp -> (tile tt, strip cs, sub csub); lane -> (lq,lr)
    const int tt = wid>>3, cs = (wid&7)>>1, csub = wid&1;
    const uint32_t convBase = smb + (uint32_t)(tt*32768 + ((cs*2+csub)*8)*512 + lane*16);

    // MMA mapping: warp -> (tile tm, strip ms, half hf)
    const int tm = wid>>3, ms = wid&3, hf = (wid>>2)&1;
    const uint32_t aBase = smb + (uint32_t)(tm*32768 + (ms*2)*8*512 + lane*16);
    const uint32_t bhBase = smb + OFF_BH + (uint32_t)((hf*9*8)*256 + lane*8);
    const uint32_t blBase = smb + OFF_BL + (uint32_t)((hf*9*8)*256 + lane*8);

    const float2* a2 = (const float2*)alt;

    auto convert = [&](int unit){
        const int row0 = (unit*2 + tt)*128 + cs*32 + csub*16 + lq;
        #pragma unroll
        for (int kb=0; kb<8; kb++){
            int c0 = kb*16 + 2*lr, c1 = c0 + 8;
            float2 v00 = a2[(size_t)row0*64     + (c0>>1)];
            float2 v10 = a2[(size_t)(row0+8)*64 + (c0>>1)];
            float2 v01 = a2[(size_t)row0*64     + (c1>>1)];
            float2 v11 = a2[(size_t)(row0+8)*64 + (c1>>1)];
            float2 t0 = *(const float2*)(Tf + c0);
            float2 t1 = *(const float2*)(Tf + c1);
            uint32_t h0,l0,h1,l1,h2,l2,h3,l3;
            split2(v00.x+t0.x, v00.y+t0.y, h0, l0);
            split2(v10.x+t0.x, v10.y+t0.y, h1, l1);
            split2(v01.x+t1.x, v01.y+t1.y, h2, l2);
            split2(v11.x+t1.x, v11.y+t1.y, h3, l3);
            STS128(convBase + kb*512,           h0,h1,h2,h3);
            STS128(convBase + OFF_AL + kb*512,  l0,l1,l2,l3);
        }
    };

    int u = blockIdx.x;
    if (u < NUNITS) convert(u);

    while (u < NUNITS){
        __syncthreads();   // conversion visible; prev DOT consumed

        // ---- MMA: 3 terms, 2 m16-frags per warp (rows ms*32..+31)
        float acc0[9][4], acc1[9][4];
        #pragma unroll
        for (int i=0;i<9;i++){
            acc0[i][0]=0.f;acc0[i][1]=0.f;acc0[i][2]=0.f;acc0[i][3]=0.f;
            acc1[i][0]=0.f;acc1[i][1]=0.f;acc1[i][2]=0.f;acc1[i][3]=0.f;
        }
        #pragma unroll
        for (int kb=0; kb<8; kb++){
            uint32_t ah0[4], ah1[4], al0[4], al1[4];
            LDS128(ah0[0],ah0[1],ah0[2],ah0[3], aBase + kb*512);
            LDS128(ah1[0],ah1[1],ah1[2],ah1[3], aBase + 4096 + kb*512);
            LDS128(al0[0],al0[1],al0[2],al0[3], aBase + OFF_AL + kb*512);
            LDS128(al1[0],al1[1],al1[2],al1[3], aBase + OFF_AL + 4096 + kb*512);
            #pragma unroll
            for (int nb=0; nb<9; nb++){
                uint32_t bh0,bh1,bl0,bl1;
                LDS64(bh0,bh1, bhBase + (nb*8+kb)*256);
                LDS64(bl0,bl1, blBase + (nb*8+kb)*256);
                mma_bf16(acc0[nb], ah0[0],ah0[1],ah0[2],ah0[3], bh0,bh1);
                mma_bf16(acc1[nb], ah1[0],ah1[1],ah1[2],ah1[3], bh0,bh1);
                mma_bf16(acc0[nb], al0[0],al0[1],al0[2],al0[3], bh0,bh1);
                mma_bf16(acc1[nb], al1[0],al1[1],al1[2],al1[3], bh0,bh1);
                mma_bf16(acc0[nb], ah0[0],ah0[1],ah0[2],ah0[3], bl0,bl1);
                mma_bf16(acc1[nb], ah1[0],ah1[1],ah1[2],ah1[3], bl0,bl1);
            }
        }

        // ---- extract: s2/nx partials + dot columns
        float s2v[4]={0.f,0.f,0.f,0.f}, nxv[4]={0.f,0.f,0.f,0.f};
        #pragma unroll
        for (int nb=0; nb<9; nb++){
            int col = hf*72 + nb*8 + 2*lr;
            if (hf==0 || nb<7){
                float g0 = SIG2f[col], g1 = SIG2f[col+1];
                float q;
                q = acc0[nb][0]*acc0[nb][0]; s2v[0]+=q; nxv[0]=fmaf(q,g0,nxv[0]);
                q = acc0[nb][1]*acc0[nb][1]; s2v[0]+=q; nxv[0]=fmaf(q,g1,nxv[0]);
                q = acc0[nb][2]*acc0[nb][2]; s2v[1]+=q; nxv[1]=fmaf(q,g0,nxv[1]);
                q = acc0[nb][3]*acc0[nb][3]; s2v[1]+=q; nxv[1]=fmaf(q,g1,nxv[1]);
                q = acc1[nb][0]*acc1[nb][0]; s2v[2]+=q; nxv[2]=fmaf(q,g0,nxv[2]);
                q = acc1[nb][1]*acc1[nb][1]; s2v[2]+=q; nxv[2]=fmaf(q,g1,nxv[2]);
                q = acc1[nb][2]*acc1[nb][2]; s2v[3]+=q; nxv[3]=fmaf(q,g0,nxv[3]);
                q = acc1[nb][3]*acc1[nb][3]; s2v[3]+=q; nxv[3]=fmaf(q,g1,nxv[3]);
            } else {
                int kc = (nb-7)*8 + 2*lr;
                if (kc < 12){
                    int r0 = ms*32 + lq;
                    uint32_t dbase = smb + OFF_DOT + (uint32_t)(tm*128*48);
                    STS64F(dbase + (uint32_t)((r0   )*48 + kc*4), acc0[nb][0], acc0[nb][1]);
                    STS64F(dbase + (uint32_t)((r0+ 8)*48 + kc*4), acc0[nb][2], acc0[nb][3]);
                    STS64F(dbase + (uint32_t)((r0+16)*48 + kc*4), acc1[nb][0], acc1[nb][1]);
                    STS64F(dbase + (uint32_t)((r0+24)*48 + kc*4), acc1[nb][2], acc1[nb][3]);
                }
            }
        }
        const unsigned full = 0xffffffffu;
        #pragma unroll
        for (int o=1;o<4;o<<=1){
            #pragma unroll
            for (int i=0;i<4;i++){
                s2v[i] += __shfl_xor_sync(full, s2v[i], o);
                nxv[i] += __shfl_xor_sync(full, nxv[i], o);
            }
        }
        {
            float sv = (lr==0)?s2v[0]:(lr==1)?s2v[1]:(lr==2)?s2v[2]:s2v[3];
            float nv = (lr==0)?nxv[0]:(lr==1)?nxv[1]:(lr==2)?nxv[2]:nxv[3];
            int row = ms*32 + lr*8 + lq;
            S2Bf[(tm*2+hf)*128 + row] = sv;
            NXBf[(tm*2+hf)*128 + row] = nv;
        }
        __syncthreads();   // DOT/S2B/NXB ready; A frags free

        int un = u + gridDim.x;
        if (un < NUNITS) convert(un);   // LDG issues early, overlaps epilogue

        // ---- epilogue: 2 threads per read, 6 clusters each
        {
            const int r = tid>>1, h = tid&1;
            const int te = r>>7, rl = r&127;
            const int gr = (u*2 + te)*128 + rl;
            float s2 = S2Bf[(te*2)*128 + rl] + S2Bf[(te*2+1)*128 + rl];
            float nx = NXBf[(te*2)*128 + rl] + NXBf[(te*2+1)*128 + rl];
            if (h==0)
                g_scratch[gr] = -64.f*LOG2PI - slog - 0.5f*s2;
            const float* drow = DOTf + te*128*12 + rl*12;
            #pragma unroll
            for (int kk=0; kk<6; kk++){
                int k = h*6 + kk;
                float dk    = drow[k];
                float orth2 = nx - dk*dk;
                float oll   = KON[60+k] - orth2*KON[72+k];
                float z     = (KON[k] - dk)*KON[24+k];
                float lec;
                if (z > 5.f){
                    float z2=z*z, z4=z2*z2, z6=z4*z2;
                    lec = -z2 - logf(z*SQRTPI)
                          + log1pf(-1.f/(2.f*z2) + 3.f/(4.f*z4) - 15.f/(8.f*z6));
                } else {
                    lec = logf(erfcf(z));
                }
                float par = KON[36+k] + lec + KON[48+k]*(KON[12+k] - 2.f*dk);
                g_scratch[(size_t)(1+k)*RD + gr] = oll + par;
            }
        }
        u = un;
    }
}

// ---------------- K3: 2 variants per warp, all 13 components preloaded (MLP) ----------------
__global__ void reduce_kernel(float* __restrict__ out)
{
    const int lane = threadIdx.x & 31;
    const int vsel = lane>>4, rr = lane&15;
    const int b = blockIdx.x*16 + (threadIdx.x>>5)*2 + vsel;
    const unsigned full = 0xffffffffu;
    const int lo = g_off[b], hi = g_off[b+1];

    float v[KC+1];
    #pragma unroll
    for (int c=0; c<KC+1; c++) v[c] = 0.f;

    for (int rd = lo + rr; rd < hi; rd += 16){
        #pragma unroll
        for (int c=0; c<KC+1; c++)       // 13 independent LDGs -> MLP
            v[c] += g_scratch[(size_t)c*RD + rd];
    }
    // 13 independent butterfly chains within each 16-lane half
    #pragma unroll
    for (int c=0; c<KC+1; c++){
        v[c] += __shfl_xor_sync(full, v[c], 8);
        v[c] += __shfl_xor_sync(full, v[c], 4);
        v[c] += __shfl_xor_sync(full, v[c], 2);
        v[c] += __shfl_xor_sync(full, v[c], 1);
    }
    float comp = 0.f;
    #pragma unroll
    for (int c=0; c<KC+1; c++)
        if (rr == c) comp = v[c];

    float nonart = __shfl_sync(full, comp, lane & 16);
    bool isart = (rr >= 1 && rr <= KC);
    float val = comp + (isart ? g_lsm[rr-1] : 0.f);
    float m = isart ? val : -1e30f;
    #pragma unroll
    for (int o=8;o>0;o>>=1) m = fmaxf(m, __shfl_xor_sync(full, m, o));
    float e = isart ? expf(val-m) : 0.f;
    #pragma unroll
    for (int o=8;o>0;o>>=1) e += __shfl_xor_sync(full, e, o);
    float logits = m + logf(e) - nonart;

    if (rr==0)      out[b] = 20.f*tanhf(logits*(1.f/20.f));
    if (rr<=KC)     out[BV + b*(KC+1) + rr] = val;
}

// ---------------- launch ----------------
extern "C" void kernel_launch(void* const* d_in, const int* in_sizes, int n_in,
                              void* d_out, int out_size)
{
    const float* alt   = (const float*)d_in[0];
    // d_in[1] = ref_re: unused by the reference output
    const float* trans = (const float*)d_in[2];
    const float* rot   = (const float*)d_in[3];
    const float* stde  = (const float*)d_in[4];
    const float* dirs  = (const float*)d_in[5];
    const float* mu    = (const float*)d_in[6];
    const float* sig   = (const float*)d_in[7];
    const float* lam   = (const float*)d_in[8];
    const float* asd   = (const float*)d_in[9];
    const float* w     = (const float*)d_in[10];
    const int*   cnt   = (const int*)d_in[11];
    float* out = (float*)d_out;

    cudaFuncSetAttribute(main_kernel, cudaFuncAttributeMaxDynamicSharedMemorySize,
                         SMEM_BYTES);

    k01_setup<<<129, 512>>>(rot, dirs, stde, mu, sig, lam, asd, w, cnt);
    main_kernel<<<GRID_MAIN, 512, SMEM_BYTES>>>(alt, trans, rot);
    reduce_kernel<<<BV/16, 256>>>(out);
}